// round 17
// baseline (speedup 1.0000x reference)
#include <cuda_runtime.h>
#include <cstdint>

// Problem constants (fixed by the dataset)
#define NMAX    500000
#define EMAX    2000000
#define EMB     32
#define IN_DIM  65
#define TB      256
#define STRIDE  32            // ELL width; P(indegree > 32) ~ 1e-15 for this input
#define OVFCAP  8192

// Scratch (allocation-free rule: __device__ globals)
__device__ int g_novf;
__device__ __align__(128) int  g_cnt[NMAX];              // indegree (excl. self-loop)
__device__ __align__(128) int  g_ell[(size_t)NMAX * STRIDE]; // ELL: src ids (padded w/ NMAX)
__device__ __align__(128) int2 g_ovf[OVFCAP];            // overflow {dst, src}
// (dinv fp32 with low 7 mantissa bits replaced by x). Index NMAX is NEVER
// written -> stays 0.0f (zero-init) -> dummy ELL slots contribute 0.
__device__ __align__(128) unsigned g_packedf[NMAX + 1];

// ---------------------------------------------------------------------------
// K1: zero counts, out[g] = b_out[0]
// ---------------------------------------------------------------------------
__global__ void k_init(float* __restrict__ out, const float* __restrict__ b_out,
                       int N, int G) {
    int i = blockIdx.x * blockDim.x + threadIdx.x;
    if (i < N) g_cnt[i] = 0;
    if (i < G) out[i] = b_out[0];
    if (i == 0) g_novf = 0;
}

// ---------------------------------------------------------------------------
// K2: ONE pass over edges: count indegree AND scatter src into ELL slot.
// ---------------------------------------------------------------------------
__device__ __forceinline__ void fill_one(int d, int s) {
    int r = atomicAdd(&g_cnt[d], 1);
    if (r < STRIDE) {
        g_ell[(size_t)d * STRIDE + r] = s;
    } else {
        int o = atomicAdd(&g_novf, 1);
        if (o < OVFCAP) g_ovf[o] = make_int2(d, s);
    }
}

__global__ void k_degfill(const int* __restrict__ src, const int* __restrict__ dst,
                          int E) {
    int t = blockIdx.x * blockDim.x + threadIdx.x;
    int e = t * 4;
    if (e + 3 < E) {
        int4 d4 = *reinterpret_cast<const int4*>(dst + e);
        int4 s4 = *reinterpret_cast<const int4*>(src + e);
        fill_one(d4.x, s4.x);
        fill_one(d4.y, s4.y);
        fill_one(d4.z, s4.z);
        fill_one(d4.w, s4.w);
    } else {
        for (int k = e; k < E; k++) fill_one(dst[k], src[k]);
    }
}

// ---------------------------------------------------------------------------
// K3: packedf[i] = (bits(rsqrt(1+cnt)) & ~127) | x   (x stolen into mantissa,
//     rel perturbation <= 2^-17 -> negligible). Also pad ELL row to a
//     multiple of 4 with dummy index NMAX (dinv 0 -> zero contribution).
// ---------------------------------------------------------------------------
__global__ void k_pack(const int* __restrict__ x, int N) {
    int i = blockIdx.x * blockDim.x + threadIdx.x;
    if (i < N) {
        int c = g_cnt[i];
        float dinv = rsqrtf(1.0f + (float)c);
        g_packedf[i] = (__float_as_uint(dinv) & ~127u) | (unsigned)x[i];
        int m  = c < STRIDE ? c : STRIDE;
        int m4 = (m + 3) & ~3;
        for (int k = m; k < m4; k++)
            g_ell[(size_t)i * STRIDE + k] = NMAX;   // dummy (zero payload)
    }
}

// ---------------------------------------------------------------------------
// K4: 4 lanes per node, 8 EMB-columns per lane, float4 LDS (WPITCH4=9).
//     Branch-free 4-edge groups: 1 broadcast int4 ELL read, then per edge
//     1x LDG.32 payload + 2 LOP + 2x LDS.128 + 8 FFMA. No LUT, no selects.
// ---------------------------------------------------------------------------
__device__ __forceinline__ float tanha(float v) {
    float r;
    asm("tanh.approx.f32 %0, %1;" : "=f"(r) : "f"(v));
    return r;
}

#define WPITCH4 9   // float4 pitch per W row (36 floats)

__global__ void __launch_bounds__(TB)
k_aggpool(const int* __restrict__ batch,
          const float* __restrict__ W,
          const float* __restrict__ b_conv,
          const float* __restrict__ W_out,
          float* __restrict__ out, int N) {
    __shared__ float4 sW4[IN_DIM * WPITCH4];
    __shared__ float sb[EMB];
    __shared__ float so[EMB];
    {
        float* sWf = reinterpret_cast<float*>(sW4);
        for (int t = threadIdx.x; t < IN_DIM * EMB; t += blockDim.x) {
            int r = t / EMB, cc = t % EMB;
            sWf[r * (WPITCH4 * 4) + cc] = W[t];
        }
    }
    if (threadIdx.x < EMB) {
        sb[threadIdx.x] = b_conv[threadIdx.x];
        so[threadIdx.x] = W_out[threadIdx.x];
    }
    __syncthreads();

    int t    = blockIdx.x * TB + threadIdx.x;
    int node = t >> 2;          // 4 lanes per node
    int sub  = t & 3;           // column group: columns [8*sub, 8*sub+8)
    if (node >= N) return;

    unsigned up = g_packedf[node];    // broadcast across the 4 lanes
    int   xi   = (int)(up & 127u);
    float dinv = __uint_as_float(up & ~127u);
    int   cnt  = g_cnt[node];         // broadcast
    int   f0   = sub * 2;             // float4 index of this lane's first quad
    const int* row_ell = g_ell + (size_t)node * STRIDE;

    float4 acc0, acc1;
    {
        const float4* row = &sW4[xi * WPITCH4 + f0];
        float4 w0 = row[0], w1 = row[1];
        acc0 = make_float4(dinv * w0.x, dinv * w0.y, dinv * w0.z, dinv * w0.w);
        acc1 = make_float4(dinv * w1.x, dinv * w1.y, dinv * w1.z, dinv * w1.w);
    }

    int m  = cnt <= STRIDE ? cnt : STRIDE;
    int m4 = (m + 3) & ~3;            // ELL row padded to this by k_pack
    for (int k = 0; k < m4; k += 4) {
        int4 q = *reinterpret_cast<const int4*>(row_ell + k);  // broadcast
        unsigned u0 = g_packedf[q.x];
        unsigned u1 = g_packedf[q.y];
        unsigned u2 = g_packedf[q.z];
        unsigned u3 = g_packedf[q.w];
        {
            float ds = __uint_as_float(u0 & ~127u);
            const float4* r = &sW4[(int)(u0 & 127u) * WPITCH4 + f0];
            float4 a0 = r[0], a1 = r[1];
            acc0.x += ds * a0.x; acc0.y += ds * a0.y; acc0.z += ds * a0.z; acc0.w += ds * a0.w;
            acc1.x += ds * a1.x; acc1.y += ds * a1.y; acc1.z += ds * a1.z; acc1.w += ds * a1.w;
        }
        {
            float ds = __uint_as_float(u1 & ~127u);
            const float4* r = &sW4[(int)(u1 & 127u) * WPITCH4 + f0];
            float4 a0 = r[0], a1 = r[1];
            acc0.x += ds * a0.x; acc0.y += ds * a0.y; acc0.z += ds * a0.z; acc0.w += ds * a0.w;
            acc1.x += ds * a1.x; acc1.y += ds * a1.y; acc1.z += ds * a1.z; acc1.w += ds * a1.w;
        }
        {
            float ds = __uint_as_float(u2 & ~127u);
            const float4* r = &sW4[(int)(u2 & 127u) * WPITCH4 + f0];
            float4 a0 = r[0], a1 = r[1];
            acc0.x += ds * a0.x; acc0.y += ds * a0.y; acc0.z += ds * a0.z; acc0.w += ds * a0.w;
            acc1.x += ds * a1.x; acc1.y += ds * a1.y; acc1.z += ds * a1.z; acc1.w += ds * a1.w;
        }
        {
            float ds = __uint_as_float(u3 & ~127u);
            const float4* r = &sW4[(int)(u3 & 127u) * WPITCH4 + f0];
            float4 a0 = r[0], a1 = r[1];
            acc0.x += ds * a0.x; acc0.y += ds * a0.y; acc0.z += ds * a0.z; acc0.w += ds * a0.w;
            acc1.x += ds * a1.x; acc1.y += ds * a1.y; acc1.z += ds * a1.z; acc1.w += ds * a1.w;
        }
    }

    // Heavy-node path (never taken on this input; correctness fallback).
    if (cnt > STRIDE) {
        int novf = g_novf;
        if (novf > OVFCAP) novf = OVFCAP;
        for (int j2 = 0; j2 < novf; j2++) {
            int2 ov = g_ovf[j2];
            if (ov.x == node) {
                unsigned u = g_packedf[ov.y];
                float ds = __uint_as_float(u & ~127u);
                const float4* rr = &sW4[(int)(u & 127u) * WPITCH4 + f0];
                float4 a0 = rr[0], a1 = rr[1];
                acc0.x += ds * a0.x; acc0.y += ds * a0.y; acc0.z += ds * a0.z; acc0.w += ds * a0.w;
                acc1.x += ds * a1.x; acc1.y += ds * a1.y; acc1.z += ds * a1.z; acc1.w += ds * a1.w;
            }
        }
    }

    int col0 = sub * 8;
    float res = 0.f;
    res += tanha(acc0.x * dinv + sb[col0 + 0]) * so[col0 + 0];
    res += tanha(acc0.y * dinv + sb[col0 + 1]) * so[col0 + 1];
    res += tanha(acc0.z * dinv + sb[col0 + 2]) * so[col0 + 2];
    res += tanha(acc0.w * dinv + sb[col0 + 3]) * so[col0 + 3];
    res += tanha(acc1.x * dinv + sb[col0 + 4]) * so[col0 + 4];
    res += tanha(acc1.y * dinv + sb[col0 + 5]) * so[col0 + 5];
    res += tanha(acc1.z * dinv + sb[col0 + 6]) * so[col0 + 6];
    res += tanha(acc1.w * dinv + sb[col0 + 7]) * so[col0 + 7];

    // reduce across the 4 lanes of this node
    res += __shfl_xor_sync(0xffffffffu, res, 1);
    res += __shfl_xor_sync(0xffffffffu, res, 2);
    if (sub == 0) atomicAdd(&out[batch[node]], res);
}

// ---------------------------------------------------------------------------
// Launch
// Inputs: 0:x[N] i32, 1:edge_index[2E] i32, 2:batch[N] i32,
//         3:W[65*32] f32, 4:b_conv[32] f32, 5:W_out[32] f32, 6:b_out[1] f32
// Output: out[G] f32
// ---------------------------------------------------------------------------
extern "C" void kernel_launch(void* const* d_in, const int* in_sizes, int n_in,
                              void* d_out, int out_size) {
    const int*   x     = (const int*)d_in[0];
    const int*   eidx  = (const int*)d_in[1];
    const int*   batch = (const int*)d_in[2];
    const float* W     = (const float*)d_in[3];
    const float* bconv = (const float*)d_in[4];
    const float* Wout  = (const float*)d_in[5];
    const float* bout  = (const float*)d_in[6];
    float* out = (float*)d_out;

    int N = in_sizes[0];
    int E = in_sizes[1] / 2;
    int G = out_size;

    const int* src = eidx;
    const int* dst = eidx + E;

    int initN = N > G ? N : G;
    int nbE4  = ((E + 3) / 4 + TB - 1) / TB;
    int nbN   = (N + TB - 1) / TB;
    int nbN4  = (int)(((size_t)N * 4 + TB - 1) / TB);

    k_init   <<<(initN + TB - 1) / TB, TB>>>(out, bout, N, G);
    k_degfill<<<nbE4, TB>>>(src, dst, E);
    k_pack   <<<nbN, TB>>>(x, N);
    k_aggpool<<<nbN4, TB>>>(batch, W, bconv, Wout, out, N);
}